// round 2
// baseline (speedup 1.0000x reference)
#include <cuda_runtime.h>

namespace {

constexpr int IMG_H  = 512;
constexpr int IMG_W  = 512;
constexpr int NPLANE = 48;            // 16 * 3
constexpr int TILE_W = 128;
constexpr int TILE_H = 128;
constexpr int THREADS = 128;
constexpr int HALO = 5;
constexpr int IN_ROWS = TILE_H + 2 * HALO;          // 138 input rows needed
constexpr int NGROUPS = (IN_ROWS + 10) / 11;        // 13 groups of 11 staged rows
constexpr int SROW = TILE_W + 2 * HALO;             // 138 floats per staged row
constexpr int GRID_X = IMG_W / TILE_W;              // 4
constexpr int GRID_Y = IMG_H / TILE_H;              // 4
constexpr int NBLOCKS = GRID_X * GRID_Y * NPLANE;   // 768
constexpr float C1v = 0.01f * 0.01f;
constexpr float C2v = 0.03f * 0.03f;
constexpr double NPIX = 12582912.0;                 // 16*3*512*512

// Normalized 11-tap Gaussian, sigma = 1.5 (matches reference float32 window
// to < 1 ulp). Compile-time constants -> FFMA-imm (rt_SMSP = 1) in SASS.
__device__ constexpr float GW[11] = {
    0.0010283784f, 0.0075987582f, 0.0360008038f, 0.1093606949f, 0.2130055428f,
    0.2660117149f, 0.2130055428f, 0.1093606949f, 0.0360008038f, 0.0075987582f,
    0.0010283784f};

} // namespace

__device__ float g_partials[NBLOCKS * 2];

__global__ __launch_bounds__(THREADS)
void ssim_main(const float* __restrict__ img1, const float* __restrict__ img2) {
    __shared__ float sx[11 * SROW];
    __shared__ float sy[11 * SROW];
    __shared__ float sred[8];

    const int tid = threadIdx.x;
    const int c0 = blockIdx.x * TILE_W;
    const int r0 = blockIdx.y * TILE_H;
    const float* p1 = img1 + (size_t)blockIdx.z * (IMG_H * IMG_W);
    const float* p2 = img2 + (size_t)blockIdx.z * (IMG_H * IMG_W);

    // Vertical ring accumulators: slot = output_row % 11. Statically indexed
    // (inner loops fully unrolled, group size == 11) -> stay in registers.
    float a1[11], a2[11], axx[11], ayy[11], axy[11];
#pragma unroll
    for (int i = 0; i < 11; ++i) {
        a1[i] = 0.f; a2[i] = 0.f; axx[i] = 0.f; ayy[i] = 0.f; axy[i] = 0.f;
    }

    float ssim_sum = 0.f;
    float l1_sum = 0.f;

    for (int t = 0; t < NGROUPS; ++t) {
        __syncthreads();   // previous group's SMEM fully consumed
        const int rbase = r0 - HALO + t * 11;
        for (int idx = tid; idx < 11 * SROW; idx += THREADS) {
            const int j = idx / SROW;
            const int col = idx - j * SROW;
            const int gr = rbase + j;
            const int gc = c0 - HALO + col;
            float xv = 0.f, yv = 0.f;
            if ((unsigned)gr < (unsigned)IMG_H && (unsigned)gc < (unsigned)IMG_W) {
                const int o = gr * IMG_W + gc;
                xv = __ldg(p1 + o);
                yv = __ldg(p2 + o);
            }
            sx[idx] = xv;
            sy[idx] = yv;
        }
        __syncthreads();

#pragma unroll
        for (int j = 0; j < 11; ++j) {
            const int ir = t * 11 + j;   // input row index within 0..142

            // Horizontal 11-tap conv of x, y, x^2, y^2, x*y (on-the-fly products)
            float hx = 0.f, hy = 0.f, hxx = 0.f, hyy = 0.f, hxy = 0.f;
#pragma unroll
            for (int k = 0; k < 11; ++k) {
                const float xv = sx[j * SROW + tid + k];
                const float yv = sy[j * SROW + tid + k];
                const float w = GW[k];
                hx  = fmaf(w, xv, hx);
                hy  = fmaf(w, yv, hy);
                hxx = fmaf(w, xv * xv, hxx);
                hyy = fmaf(w, yv * yv, hyy);
                hxy = fmaf(w, xv * yv, hxy);
            }

            // L1 term: exactly once per pixel (rows r0..r0+TILE_H-1 <=> ir in [5, TILE_H+5))
            if (ir >= HALO && ir < TILE_H + HALO) {
                const float xc = sx[j * SROW + tid + HALO];
                const float yc = sy[j * SROW + tid + HALO];
                l1_sum += fabsf(xc - yc);
            }

            // Vertical ring accumulation. Output row oy receives contributions
            // from ir = oy..oy+10 with weight GW[ir-oy]. Phase p = ir%11 == j.
#pragma unroll
            for (int dy = 0; dy < 11; ++dy) {
                const int s = (j - dy + 11) % 11;   // slot = (ir-dy) % 11, static
                const float w = GW[dy];
                if (dy == 0) {   // first touch of freshly-freed slot: assign
                    a1[s] = w * hx;  a2[s] = w * hy;
                    axx[s] = w * hxx; ayy[s] = w * hyy; axy[s] = w * hxy;
                } else {
                    a1[s]  = fmaf(w, hx,  a1[s]);
                    a2[s]  = fmaf(w, hy,  a2[s]);
                    axx[s] = fmaf(w, hxx, axx[s]);
                    ayy[s] = fmaf(w, hyy, ayy[s]);
                    axy[s] = fmaf(w, hxy, axy[s]);
                }
            }

            // Output row oy = ir-10 completed this iteration (slot (j+1)%11)
            if (ir >= 10 && ir < TILE_H + 10) {
                const int s = (j + 1) % 11;
                const float mu1 = a1[s], mu2 = a2[s];
                const float m11 = mu1 * mu1;
                const float m22 = mu2 * mu2;
                const float m12 = mu1 * mu2;
                const float s1  = axx[s] - m11;
                const float s2  = ayy[s] - m22;
                const float s12 = axy[s] - m12;
                const float num = (2.f * m12 + C1v) * (2.f * s12 + C2v);
                const float den = (m11 + m22 + C1v) * (s1 + s2 + C2v);
                ssim_sum += num / den;
            }
        }
    }

    // Block reduction: warp shuffles then cross-warp via SMEM.
#pragma unroll
    for (int off = 16; off; off >>= 1) {
        ssim_sum += __shfl_xor_sync(0xffffffffu, ssim_sum, off);
        l1_sum   += __shfl_xor_sync(0xffffffffu, l1_sum, off);
    }
    const int warp = tid >> 5;
    const int lane = tid & 31;
    if (lane == 0) {
        sred[warp] = ssim_sum;
        sred[warp + 4] = l1_sum;
    }
    __syncthreads();
    if (tid == 0) {
        const int bid = (blockIdx.z * GRID_Y + blockIdx.y) * GRID_X + blockIdx.x;
        g_partials[2 * bid]     = sred[0] + sred[1] + sred[2] + sred[3];
        g_partials[2 * bid + 1] = sred[4] + sred[5] + sred[6] + sred[7];
    }
}

__global__ __launch_bounds__(256)
void ssim_finalize(float* __restrict__ out) {
    __shared__ double sd[16];
    double s = 0.0, l = 0.0;
    for (int i = threadIdx.x; i < NBLOCKS; i += 256) {
        s += (double)g_partials[2 * i];
        l += (double)g_partials[2 * i + 1];
    }
#pragma unroll
    for (int off = 16; off; off >>= 1) {
        s += __shfl_xor_sync(0xffffffffu, s, off);
        l += __shfl_xor_sync(0xffffffffu, l, off);
    }
    const int warp = threadIdx.x >> 5;
    const int lane = threadIdx.x & 31;
    if (lane == 0) { sd[warp] = s; sd[warp + 8] = l; }
    __syncthreads();
    if (threadIdx.x == 0) {
        double ss = 0.0, ll = 0.0;
#pragma unroll
        for (int w = 0; w < 8; ++w) { ss += sd[w]; ll += sd[w + 8]; }
        out[0] = (float)(ll / NPIX + 1.0 - ss / NPIX);
    }
}

extern "C" void kernel_launch(void* const* d_in, const int* in_sizes, int n_in,
                              void* d_out, int out_size) {
    (void)in_sizes; (void)n_in; (void)out_size;
    const float* img1 = (const float*)d_in[0];
    const float* img2 = (const float*)d_in[1];
    dim3 grid(GRID_X, GRID_Y, NPLANE);
    ssim_main<<<grid, THREADS>>>(img1, img2);
    ssim_finalize<<<1, 256>>>((float*)d_out);
}

// round 3
// speedup vs baseline: 1.0253x; 1.0253x over previous
#include <cuda_runtime.h>

namespace {

constexpr int IMG_H  = 512;
constexpr int IMG_W  = 512;
constexpr int NPLANE = 48;            // 16 * 3
constexpr int TILE_W = 256;           // 2 cols per thread, 128 threads
constexpr int TILE_H = 64;
constexpr int THREADS = 128;
constexpr int HALO = 5;
constexpr int IN_ROWS = TILE_H + 2 * HALO;          // 74 input rows needed
constexpr int NGROUPS = (IN_ROWS + 10) / 11;        // 7 groups of 11 staged rows
constexpr int SROW = TILE_W + 2 * HALO;             // 266 floats (even -> LDS.64 ok)
constexpr int GRID_X = IMG_W / TILE_W;              // 2
constexpr int GRID_Y = IMG_H / TILE_H;              // 8
constexpr int NBLOCKS = GRID_X * GRID_Y * NPLANE;   // 768
constexpr float C1v = 0.01f * 0.01f;
constexpr float C2v = 0.03f * 0.03f;
constexpr double NPIX = 12582912.0;                 // 16*3*512*512

// Normalized 11-tap Gaussian, sigma = 1.5 (matches reference fp32 window).
__device__ constexpr float GW[11] = {
    0.0010283784f, 0.0075987582f, 0.0360008038f, 0.1093606949f, 0.2130055428f,
    0.2660117149f, 0.2130055428f, 0.1093606949f, 0.0360008038f, 0.0075987582f,
    0.0010283784f};

} // namespace

// ---- packed f32x2 helpers (SASS FFMA2 / FMUL2 — PTX-only forms) ----
#define FMA2(d, a, b, c) \
    asm("fma.rn.f32x2 %0, %1, %2, %3;" : "=l"(d) : "l"(a), "l"(b), "l"(c))
#define MUL2(d, a, b) \
    asm("mul.rn.f32x2 %0, %1, %2;" : "=l"(d) : "l"(a), "l"(b))
#define PACK2(d, lo, hi) \
    asm("mov.b64 %0, {%1, %2};" : "=l"(d) : "r"(__float_as_uint(lo)), "r"(__float_as_uint(hi)))
#define UNPACK2(lo, hi, d) \
    do { unsigned _ulo, _uhi; \
         asm("mov.b64 {%0, %1}, %2;" : "=r"(_ulo), "=r"(_uhi) : "l"(d)); \
         lo = __uint_as_float(_ulo); hi = __uint_as_float(_uhi); } while (0)

__device__ float g_partials[NBLOCKS * 2];
__device__ unsigned int g_count = 0;

__global__ __launch_bounds__(THREADS)
void ssim_main(const float* __restrict__ img1, const float* __restrict__ img2,
               float* __restrict__ out) {
    __shared__ __align__(16) float sx[11 * SROW];
    __shared__ __align__(16) float sy[11 * SROW];
    __shared__ float sred[8];
    __shared__ bool s_last;

    const int tid = threadIdx.x;
    const int c0 = blockIdx.x * TILE_W;
    const int r0 = blockIdx.y * TILE_H;
    const float* p1 = img1 + (size_t)blockIdx.z * (IMG_H * IMG_W);
    const float* p2 = img2 + (size_t)blockIdx.z * (IMG_H * IMG_W);

    // Packed Gaussian weights (w, w) in 64-bit regs.
    unsigned long long wp[11];
#pragma unroll
    for (int k = 0; k < 11; ++k) PACK2(wp[k], GW[k], GW[k]);

    // Vertical ring accumulators (packed pairs), slot = output_row % 11.
    unsigned long long a1p[11], a2p[11], axxp[11], ayyp[11], axyp[11];
#pragma unroll
    for (int i = 0; i < 11; ++i) {
        a1p[i] = 0ull; a2p[i] = 0ull; axxp[i] = 0ull; ayyp[i] = 0ull; axyp[i] = 0ull;
    }

    float ssim_sum = 0.f;
    float l1_sum = 0.f;

    for (int t = 0; t < NGROUPS; ++t) {
        __syncthreads();   // previous group's SMEM fully consumed
        const int rbase = r0 - HALO + t * 11;
        for (int idx = tid; idx < 11 * SROW; idx += THREADS) {
            const int j = idx / SROW;
            const int col = idx - j * SROW;
            const int gr = rbase + j;
            const int gc = c0 - HALO + col;
            float xv = 0.f, yv = 0.f;
            if ((unsigned)gr < (unsigned)IMG_H && (unsigned)gc < (unsigned)IMG_W) {
                const int o = gr * IMG_W + gc;
                xv = __ldg(p1 + o);
                yv = __ldg(p2 + o);
            }
            sx[idx] = xv;
            sy[idx] = yv;
        }
        __syncthreads();

#pragma unroll
        for (int j = 0; j < 11; ++j) {
            const int ir = t * 11 + j;   // staged input row index
            if (ir >= IN_ROWS) break;    // uniform: skip unused tail rows

            // Load the 12-float window for this thread's 2 columns (6x LDS.64).
            float xv[12], yv[12];
            {
                const float2* bx = reinterpret_cast<const float2*>(&sx[j * SROW + 2 * tid]);
                const float2* by = reinterpret_cast<const float2*>(&sy[j * SROW + 2 * tid]);
#pragma unroll
                for (int i = 0; i < 6; ++i) {
                    float2 v = bx[i]; xv[2 * i] = v.x; xv[2 * i + 1] = v.y;
                    float2 w = by[i]; yv[2 * i] = w.x; yv[2 * i + 1] = w.y;
                }
            }

            // Horizontal 11-tap conv of x, y, x^2, y^2, x*y — packed pairs.
            unsigned long long hx, hy, hxx, hyy, hxy;
#pragma unroll
            for (int k = 0; k < 11; ++k) {
                unsigned long long xp, yp, xxp, yyp, xyp;
                PACK2(xp, xv[k], xv[k + 1]);
                PACK2(yp, yv[k], yv[k + 1]);
                MUL2(xxp, xp, xp);
                MUL2(yyp, yp, yp);
                MUL2(xyp, xp, yp);
                if (k == 0) {
                    MUL2(hx, wp[0], xp);  MUL2(hy, wp[0], yp);
                    MUL2(hxx, wp[0], xxp); MUL2(hyy, wp[0], yyp); MUL2(hxy, wp[0], xyp);
                } else {
                    FMA2(hx,  wp[k], xp,  hx);
                    FMA2(hy,  wp[k], yp,  hy);
                    FMA2(hxx, wp[k], xxp, hxx);
                    FMA2(hyy, wp[k], yyp, hyy);
                    FMA2(hxy, wp[k], xyp, hxy);
                }
            }

            // L1 term: once per pixel (center cols = window offsets 5,6).
            if (ir >= HALO && ir < TILE_H + HALO) {
                l1_sum += fabsf(xv[5] - yv[5]) + fabsf(xv[6] - yv[6]);
            }

            // Vertical ring accumulation (packed). slot = (ir - dy) % 11, static.
#pragma unroll
            for (int dy = 0; dy < 11; ++dy) {
                const int s = (j - dy + 11) % 11;
                if (dy == 0) {   // first touch of freshly-freed slot: assign
                    MUL2(a1p[s],  wp[0], hx);
                    MUL2(a2p[s],  wp[0], hy);
                    MUL2(axxp[s], wp[0], hxx);
                    MUL2(ayyp[s], wp[0], hyy);
                    MUL2(axyp[s], wp[0], hxy);
                } else {
                    FMA2(a1p[s],  wp[dy], hx,  a1p[s]);
                    FMA2(a2p[s],  wp[dy], hy,  a2p[s]);
                    FMA2(axxp[s], wp[dy], hxx, axxp[s]);
                    FMA2(ayyp[s], wp[dy], hyy, ayyp[s]);
                    FMA2(axyp[s], wp[dy], hxy, axyp[s]);
                }
            }

            // Output row oy = ir-10 completed this iteration (slot (j+1)%11).
            if (ir >= 10 && ir < TILE_H + 10) {
                const int s = (j + 1) % 11;
                float mu1a, mu1b, mu2a, mu2b, exxa, exxb, eyya, eyyb, exya, exyb;
                UNPACK2(mu1a, mu1b, a1p[s]);
                UNPACK2(mu2a, mu2b, a2p[s]);
                UNPACK2(exxa, exxb, axxp[s]);
                UNPACK2(eyya, eyyb, ayyp[s]);
                UNPACK2(exya, exyb, axyp[s]);
                {
                    const float m11 = mu1a * mu1a, m22 = mu2a * mu2a, m12 = mu1a * mu2a;
                    const float s1 = exxa - m11, s2 = eyya - m22, s12 = exya - m12;
                    const float num = (2.f * m12 + C1v) * (2.f * s12 + C2v);
                    const float den = (m11 + m22 + C1v) * (s1 + s2 + C2v);
                    ssim_sum += __fdividef(num, den);
                }
                {
                    const float m11 = mu1b * mu1b, m22 = mu2b * mu2b, m12 = mu1b * mu2b;
                    const float s1 = exxb - m11, s2 = eyyb - m22, s12 = exyb - m12;
                    const float num = (2.f * m12 + C1v) * (2.f * s12 + C2v);
                    const float den = (m11 + m22 + C1v) * (s1 + s2 + C2v);
                    ssim_sum += __fdividef(num, den);
                }
            }
        }
    }

    // Block reduction: warp shuffles then cross-warp via SMEM.
#pragma unroll
    for (int off = 16; off; off >>= 1) {
        ssim_sum += __shfl_xor_sync(0xffffffffu, ssim_sum, off);
        l1_sum   += __shfl_xor_sync(0xffffffffu, l1_sum, off);
    }
    const int warp = tid >> 5;
    const int lane = tid & 31;
    if (lane == 0) {
        sred[warp] = ssim_sum;
        sred[warp + 4] = l1_sum;
    }
    __syncthreads();
    if (tid == 0) {
        const int bid = (blockIdx.z * GRID_Y + blockIdx.y) * GRID_X + blockIdx.x;
        g_partials[2 * bid]     = sred[0] + sred[1] + sred[2] + sred[3];
        g_partials[2 * bid + 1] = sred[4] + sred[5] + sred[6] + sred[7];
        __threadfence();
        // Self-resetting completion counter: wraps to 0 when old == NBLOCKS-1.
        const unsigned old = atomicInc(&g_count, NBLOCKS - 1);
        s_last = (old == NBLOCKS - 1);
    }
    __syncthreads();

    // Last block to finish folds the deterministic final reduction (fixed
    // read order over the completed partials array).
    if (s_last) {
        __shared__ double sd[8];
        double s = 0.0, l = 0.0;
        for (int i = tid; i < NBLOCKS; i += THREADS) {
            s += (double)g_partials[2 * i];
            l += (double)g_partials[2 * i + 1];
        }
#pragma unroll
        for (int off = 16; off; off >>= 1) {
            s += __shfl_xor_sync(0xffffffffu, s, off);
            l += __shfl_xor_sync(0xffffffffu, l, off);
        }
        if (lane == 0) { sd[warp] = s; sd[warp + 4] = l; }
        __syncthreads();
        if (tid == 0) {
            double ss = 0.0, ll = 0.0;
#pragma unroll
            for (int w = 0; w < 4; ++w) { ss += sd[w]; ll += sd[w + 4]; }
            out[0] = (float)(ll / NPIX + 1.0 - ss / NPIX);
        }
    }
}

extern "C" void kernel_launch(void* const* d_in, const int* in_sizes, int n_in,
                              void* d_out, int out_size) {
    (void)in_sizes; (void)n_in; (void)out_size;
    const float* img1 = (const float*)d_in[0];
    const float* img2 = (const float*)d_in[1];
    dim3 grid(GRID_X, GRID_Y, NPLANE);
    ssim_main<<<grid, THREADS>>>(img1, img2, (float*)d_out);
}